// round 3
// baseline (speedup 1.0000x reference)
#include <cuda_runtime.h>
#include <math.h>
#include <stdint.h>

#define NN 50000
#define EE 800000
#define TT 12
#define D  128
#define G4 (4*D)   // 512 gates

// ---------------- scratch (device globals: no allocation allowed) ----------------
__device__ float g_norm_src[NN];
__device__ float g_norm_dst[NN];
__device__ int   g_ocnt[NN];
__device__ int   g_cnt[NN + 1];
__device__ int   g_rowptr[NN + 1];
__device__ int   g_cursor[NN];
__device__ int   g_srcsorted[EE];
__device__ __align__(16) float g_x[(size_t)NN * D];       // layer activations
__device__ __align__(16) float g_m[(size_t)NN * D];       // spmm output
__device__ __align__(16) float g_h0[(size_t)NN * D];      // LSTM h ping
__device__ __align__(16) float g_h1[(size_t)NN * D];      // LSTM h pong
__device__ __align__(16) float g_cstate[(size_t)NN * D];  // LSTM c
__device__ __align__(16) float g_Wl[(size_t)G4 * 256];    // permuted [W_ih|W_hh], quad-interleaved rows
__device__ float g_bias_p[G4];                            // permuted b_ih + b_hh
__device__ float g_hs[TT * D];                            // hs accumulators

// ---------------- helpers ----------------
__device__ __forceinline__ float gelu_exact(float v) {
    return 0.5f * v * (1.0f + erff(v * 0.70710678118654752f));
}
__device__ __forceinline__ float sigmoidf_(float v) {
    return 1.0f / (1.0f + __expf(-v));
}
__device__ __forceinline__ uint32_t f2tf32(float x) {
    uint32_t r;
    asm("cvt.rna.tf32.f32 %0, %1;" : "=r"(r) : "f"(x));
    return r;
}
__device__ __forceinline__ void split_tf32(float x, uint32_t& hi, uint32_t& lo) {
    hi = f2tf32(x);
    lo = f2tf32(x - __uint_as_float(hi));
}
__device__ __forceinline__ void mma8(float (&c)[4], uint4 a, uint32_t b0, uint32_t b1) {
    asm volatile(
        "mma.sync.aligned.m16n8k8.row.col.f32.tf32.tf32.f32 "
        "{%0,%1,%2,%3},{%4,%5,%6,%7},{%8,%9},{%0,%1,%2,%3};\n"
        : "+f"(c[0]), "+f"(c[1]), "+f"(c[2]), "+f"(c[3])
        : "r"(a.x), "r"(a.y), "r"(a.z), "r"(a.w), "r"(b0), "r"(b1));
}

// ---------------- init ----------------
__global__ void init_kernel(float* __restrict__ out_ht) {
    int i = blockIdx.x * blockDim.x + threadIdx.x;
    if (i < NN * D) {
        g_h0[i] = 0.0f;
        g_cstate[i] = 0.0f;
        out_ht[i] = 0.0f;
    }
    if (i < NN) { g_ocnt[i] = 0; g_cnt[i] = 0; }
    if (i == 0) g_cnt[NN] = 0;
    if (i < TT * D) g_hs[i] = 0.0f;
}

__global__ void hist_kernel(const int* __restrict__ src, const int* __restrict__ dst) {
    int e = blockIdx.x * blockDim.x + threadIdx.x;
    if (e < EE) {
        atomicAdd(&g_ocnt[src[e]], 1);
        atomicAdd(&g_cnt[dst[e]], 1);
    }
}

__global__ void norm_kernel() {
    int i = blockIdx.x * blockDim.x + threadIdx.x;
    if (i < NN) {
        g_norm_src[i] = rsqrtf(fmaxf((float)g_ocnt[i], 1.0f));
        g_norm_dst[i] = rsqrtf(fmaxf((float)g_cnt[i], 1.0f));
    }
}

// Build permuted LSTM weight matrix: row (j*4+g) = original row (g*128+j),
// cols 0..127 = w_ih, 128..255 = w_hh. Same permutation for bias.
__global__ void wperm_kernel(const float* __restrict__ w_ih, const float* __restrict__ w_hh,
                             const float* __restrict__ b_ih, const float* __restrict__ b_hh) {
    int idx = blockIdx.x * blockDim.x + threadIdx.x;
    if (idx >= G4 * 256) return;
    int row_out = idx >> 8;
    int k = idx & 255;
    int j = row_out >> 2;
    int g = row_out & 3;
    int row_in = g * D + j;
    float v = (k < D) ? w_ih[row_in * D + k] : w_hh[row_in * D + (k - D)];
    g_Wl[(size_t)row_out * 256 + k] = v;
    if (k == 0) g_bias_p[row_out] = b_ih[row_in] + b_hh[row_in];
}

// single-block exclusive scan of g_cnt[0..NN) -> g_rowptr, init cursor
__global__ void scan_kernel() {
    __shared__ int ps[1024];
    const int CH = (NN + 1023) / 1024;
    int t = threadIdx.x;
    int beg = t * CH;
    int end = min(beg + CH, NN);
    int s = 0;
    for (int i = beg; i < end; i++) s += g_cnt[i];
    ps[t] = s;
    __syncthreads();
    if (t == 0) {
        int a = 0;
        for (int i = 0; i < 1024; i++) { int v = ps[i]; ps[i] = a; a += v; }
    }
    __syncthreads();
    int off = ps[t];
    for (int i = beg; i < end; i++) {
        g_rowptr[i] = off;
        g_cursor[i] = off;
        off += g_cnt[i];
    }
    if (t == 1023) g_rowptr[NN] = off;
}

__global__ void scatter_kernel(const int* __restrict__ src, const int* __restrict__ dst) {
    int e = blockIdx.x * blockDim.x + threadIdx.x;
    if (e < EE) {
        int d = dst[e];
        int p = atomicAdd(&g_cursor[d], 1);
        g_srcsorted[p] = src[e];
    }
}

// ---------------- SpMM: m[d] = norm_dst[d] * sum_{e: dst=d} norm_src[src] * X[src]
__global__ __launch_bounds__(256) void spmm_kernel(const float* __restrict__ X, int ldx,
                                                   float* __restrict__ M) {
    int w = (blockIdx.x * blockDim.x + threadIdx.x) >> 5;
    int lane = threadIdx.x & 31;
    if (w >= NN) return;
    int s0 = g_rowptr[w];
    int s1 = g_rowptr[w + 1];
    float4 acc = make_float4(0.f, 0.f, 0.f, 0.f);
    for (int base = s0; base < s1; base += 32) {
        int n = min(32, s1 - base);
        int s = 0; float ns = 0.f;
        if (lane < n) {
            s = g_srcsorted[base + lane];
            ns = g_norm_src[s];
        }
        for (int j = 0; j < n; j++) {
            int   sj = __shfl_sync(0xffffffffu, s, j);
            float nj = __shfl_sync(0xffffffffu, ns, j);
            float4 v = *(const float4*)(X + (size_t)sj * ldx + lane * 4);
            acc.x += v.x * nj; acc.y += v.y * nj;
            acc.z += v.z * nj; acc.w += v.w * nj;
        }
    }
    float nd = g_norm_dst[w];
    float4 o = make_float4(acc.x * nd, acc.y * nd, acc.z * nd, acc.w * nd);
    *(float4*)(M + (size_t)w * D + lane * 4) = o;
}

// ==================================================================================
// 3xTF32 tensor-core GEMM. BM=128, BN=128, BK=16, 256 threads (8 warps, 2x4),
// warp tile 64x32, mma.m16n8k8. A split into fp32->tf32 hi/lo at staging.
// MODE 0: graph conv  C = gelu(A@B + bias), B is [K][128] row-major (K=128),
//         optional column-sum into hsacc.
// MODE 1: LSTM gates  gates = [x_t | h] @ Wl^T + bias_p (Wl [512][256], quad-permuted),
//         fused cell epilogue updates cstate, hout, htacc. K=256, grid.y=4.
// ==================================================================================
template <int MODE>
__global__ __launch_bounds__(256) void gemm3x_kernel(
    const float* __restrict__ A0, int lda0,    // rows of A, first 128 k-cols
    const float* __restrict__ A1,              // MODE1: h input (ld 128)
    const float* __restrict__ B,
    const float* __restrict__ bias,
    float* __restrict__ C,                     // MODE0 output
    float* __restrict__ hsacc,                 // MODE0 colsum target (or null)
    float* __restrict__ cstate,                // MODE1
    float* __restrict__ hout,                  // MODE1
    float* __restrict__ htacc)                 // MODE1
{
    constexpr int KT = MODE ? 256 : 128;
    __shared__ __align__(16) uint32_t sh[8192];            // 32 KB
    uint32_t* As_hi = sh;                                  // 16 frags * 32 * 4
    uint32_t* As_lo = sh + 2048;
    uint32_t* Bs_hi = sh + 4096;                           // 32 frags * 32 * 2
    uint32_t* Bs_lo = sh + 6144;
    float* gtile = (float*)sh;                             // epilogue: [64][128]

    const int tid = threadIdx.x;
    const int lane = tid & 31;
    const int warpId = tid >> 5;
    const int warpM = warpId >> 2;    // 0..1
    const int warpN = warpId & 3;     // 0..3
    const int rowBase = blockIdx.x * 128;
    const int colBase = blockIdx.y * 128;

    float acc[4][4][4];
#pragma unroll
    for (int a = 0; a < 4; a++)
#pragma unroll
        for (int b = 0; b < 4; b++)
#pragma unroll
            for (int c = 0; c < 4; c++) acc[a][b][c] = 0.f;

    for (int ch = 0; ch < KT / 16; ch++) {
        const int kc = ch * 16;
        // ---- stage A (128 rows x 16 k), split hi/lo, fragment-permuted ----
        {
            int r = tid >> 1;
            int kq = (tid & 1) * 8;
            const float* src;
            int ld, kk;
            if (MODE == 1 && kc >= 128) { src = A1; ld = D; kk = kc - 128 + kq; }
            else                        { src = A0; ld = lda0; kk = kc + kq; }
            int grow = rowBase + r;
            float4 v0 = make_float4(0.f, 0.f, 0.f, 0.f);
            float4 v1 = v0;
            if (grow < NN) {
                v0 = *(const float4*)(src + (size_t)grow * ld + kk);
                v1 = *(const float4*)(src + (size_t)grow * ld + kk + 4);
            }
            float vals[8] = {v0.x, v0.y, v0.z, v0.w, v1.x, v1.y, v1.z, v1.w};
            int mi = r >> 4;
#pragma unroll
            for (int j = 0; j < 8; j++) {
                int kl = kq + j;
                uint32_t hi, lo;
                split_tf32(vals[j], hi, lo);
                int ki = kl >> 3;
                int l = (r & 7) * 4 + (kl & 3);
                int rg = ((r >> 3) & 1) | (((kl >> 2) & 1) << 1);
                int ad = ((mi * 2 + ki) * 32 + l) * 4 + rg;
                As_hi[ad] = hi;
                As_lo[ad] = lo;
            }
        }
        // ---- stage B (16 k x 128 n) ----
        if (MODE == 0) {
            int kb = tid >> 4;
            int n0 = (tid & 15) * 8;
            const float* bp = B + (size_t)(kc + kb) * 128 + n0;
            float4 v0 = *(const float4*)bp;
            float4 v1 = *(const float4*)(bp + 4);
            float vals[8] = {v0.x, v0.y, v0.z, v0.w, v1.x, v1.y, v1.z, v1.w};
            int ki = kb >> 3;
#pragma unroll
            for (int j = 0; j < 8; j++) {
                int n = n0 + j;
                uint32_t hi, lo;
                split_tf32(vals[j], hi, lo);
                int ni = n >> 3;
                int l = (n & 7) * 4 + (kb & 3);
                int rg = (kb >> 2) & 1;
                int ad = ((ni * 2 + ki) * 32 + l) * 2 + rg;
                Bs_hi[ad] = hi;
                Bs_lo[ad] = lo;
            }
        } else {
            int n = tid >> 1;
            int kq = (tid & 1) * 8;
            const float* bp = B + (size_t)(colBase + n) * 256 + kc + kq;
            float4 v0 = *(const float4*)bp;
            float4 v1 = *(const float4*)(bp + 4);
            float vals[8] = {v0.x, v0.y, v0.z, v0.w, v1.x, v1.y, v1.z, v1.w};
            int ni = n >> 3;
#pragma unroll
            for (int j = 0; j < 8; j++) {
                int kl = kq + j;
                uint32_t hi, lo;
                split_tf32(vals[j], hi, lo);
                int ki = kl >> 3;
                int l = (n & 7) * 4 + (kl & 3);
                int rg = (kl >> 2) & 1;
                int ad = ((ni * 2 + ki) * 32 + l) * 2 + rg;
                Bs_hi[ad] = hi;
                Bs_lo[ad] = lo;
            }
        }
        __syncthreads();
        // ---- compute: 2 k8 steps, 3xTF32 ----
#pragma unroll
        for (int ki = 0; ki < 2; ki++) {
            uint4 ah[4], al[4];
#pragma unroll
            for (int mi = 0; mi < 4; mi++) {
                int fid = ((warpM * 4 + mi) * 2 + ki);
                ah[mi] = ((const uint4*)As_hi)[fid * 32 + lane];
                al[mi] = ((const uint4*)As_lo)[fid * 32 + lane];
            }
#pragma unroll
            for (int ni = 0; ni < 4; ni++) {
                int fid = ((warpN * 4 + ni) * 2 + ki);
                uint2 bh = ((const uint2*)Bs_hi)[fid * 32 + lane];
                uint2 bl = ((const uint2*)Bs_lo)[fid * 32 + lane];
#pragma unroll
                for (int mi = 0; mi < 4; mi++) {
                    mma8(acc[mi][ni], ah[mi], bh.x, bh.y);
                    mma8(acc[mi][ni], ah[mi], bl.x, bl.y);
                    mma8(acc[mi][ni], al[mi], bh.x, bh.y);
                }
            }
        }
        __syncthreads();
    }

    // ---- epilogue: stage through shared (coalesced global traffic), 2 row-halves ----
    float csum[4] = {0.f, 0.f, 0.f, 0.f};   // MODE0 colsum (cols fixed per thread)
    const int cq = tid & 31;

    for (int half = 0; half < 2; half++) {
        __syncthreads();
        if (warpM == half) {
#pragma unroll
            for (int mi = 0; mi < 4; mi++) {
#pragma unroll
                for (int ni = 0; ni < 4; ni++) {
                    int rloc = mi * 16 + (lane >> 2);
                    int cloc = warpN * 32 + ni * 8 + (lane & 3) * 2;
                    float b0v = bias[colBase + cloc];
                    float b1v = bias[colBase + cloc + 1];
                    gtile[rloc * 128 + cloc]           = acc[mi][ni][0] + b0v;
                    gtile[rloc * 128 + cloc + 1]       = acc[mi][ni][1] + b1v;
                    gtile[(rloc + 8) * 128 + cloc]     = acc[mi][ni][2] + b0v;
                    gtile[(rloc + 8) * 128 + cloc + 1] = acc[mi][ni][3] + b1v;
                }
            }
        }
        __syncthreads();
#pragma unroll
        for (int i = 0; i < 8; i++) {
            int e = tid + i * 256;
            int rloc = e >> 5;
            int row = rowBase + half * 64 + rloc;
            if (MODE == 0) {
                float4 gv = *(const float4*)&gtile[rloc * 128 + cq * 4];
                float4 ov;
                ov.x = gelu_exact(gv.x);
                ov.y = gelu_exact(gv.y);
                ov.z = gelu_exact(gv.z);
                ov.w = gelu_exact(gv.w);
                if (row < NN) {
                    *(float4*)(C + (size_t)row * D + cq * 4) = ov;
                    csum[0] += ov.x; csum[1] += ov.y; csum[2] += ov.z; csum[3] += ov.w;
                }
            } else {
                if (row < NN) {
                    float4 gv = *(const float4*)&gtile[rloc * 128 + cq * 4];
                    int fg = blockIdx.y * 32 + cq;
                    size_t idx = (size_t)row * D + fg;
                    float cp = cstate[idx];
                    float c = sigmoidf_(gv.y) * cp + sigmoidf_(gv.x) * tanhf(gv.z);
                    float ho = sigmoidf_(gv.w) * tanhf(c);
                    cstate[idx] = c;
                    hout[idx] = ho;
                    htacc[idx] += ho;
                }
            }
        }
    }
    if (MODE == 0 && hsacc != nullptr) {
#pragma unroll
        for (int j = 0; j < 4; j++) atomicAdd(&hsacc[cq * 4 + j], csum[j]);
    }
}

__global__ void finalize_kernel(float* __restrict__ out) {
    int idx = blockIdx.x * blockDim.x + threadIdx.x;
    if (idx < TT * D) out[idx] = g_hs[idx] * (1.0f / (float)NN);
    if (idx < NN * D) out[TT * D + idx] *= (1.0f / (float)TT);
}

// ---------------- launch ----------------
extern "C" void kernel_launch(void* const* d_in, const int* in_sizes, int n_in,
                              void* d_out, int out_size) {
    const float* h    = (const float*)d_in[0];
    const int*   src  = (const int*)d_in[1];
    const int*   dst  = (const int*)d_in[2];
    const float* Wg1  = (const float*)d_in[3];
    const float* bg1  = (const float*)d_in[4];
    const float* Wg2  = (const float*)d_in[5];
    const float* bg2  = (const float*)d_in[6];
    const float* w_ih = (const float*)d_in[7];
    const float* w_hh = (const float*)d_in[8];
    const float* b_ih = (const float*)d_in[9];
    const float* b_hh = (const float*)d_in[10];

    float* out    = (float*)d_out;
    float* out_ht = out + TT * D;

    float *pm, *px, *ph0, *ph1, *pc, *pwl, *pbp, *phs;
    cudaGetSymbolAddress((void**)&pm, g_m);
    cudaGetSymbolAddress((void**)&px, g_x);
    cudaGetSymbolAddress((void**)&ph0, g_h0);
    cudaGetSymbolAddress((void**)&ph1, g_h1);
    cudaGetSymbolAddress((void**)&pc, g_cstate);
    cudaGetSymbolAddress((void**)&pwl, g_Wl);
    cudaGetSymbolAddress((void**)&pbp, g_bias_p);
    cudaGetSymbolAddress((void**)&phs, g_hs);

    init_kernel<<<(NN * D + 255) / 256, 256>>>(out_ht);
    hist_kernel<<<(EE + 255) / 256, 256>>>(src, dst);
    norm_kernel<<<(NN + 255) / 256, 256>>>();
    wperm_kernel<<<(G4 * 256 + 255) / 256, 256>>>(w_ih, w_hh, b_ih, b_hh);
    scan_kernel<<<1, 1024>>>();
    scatter_kernel<<<(EE + 255) / 256, 256>>>(src, dst);

    const int gx = (NN + 127) / 128;           // 391
    dim3 ggrid(gx, 1);
    dim3 lgrid(gx, 4);
    int spmm_blocks = (NN * 32 + 255) / 256;

    // graph conv tower
    for (int t = 0; t < TT; t++) {
        spmm_kernel<<<spmm_blocks, 256>>>(h + t * D, TT * D, pm);
        gemm3x_kernel<0><<<ggrid, 256>>>(pm, D, nullptr, Wg1, bg1, px, nullptr,
                                         nullptr, nullptr, nullptr);
        spmm_kernel<<<spmm_blocks, 256>>>(px, D, pm);
        gemm3x_kernel<0><<<ggrid, 256>>>(pm, D, nullptr, Wg2, bg2, px, phs + t * D,
                                         nullptr, nullptr, nullptr);
    }

    // LSTM over T steps (fused gates GEMM + cell epilogue), h ping-pong
    float* hin = ph0;
    float* hout_ = ph1;
    for (int t = 0; t < TT; t++) {
        gemm3x_kernel<1><<<lgrid, 256>>>(h + t * D, TT * D, hin, pwl, pbp,
                                         nullptr, nullptr, pc, hout_, out_ht);
        float* tmp = hin; hin = hout_; hout_ = tmp;
    }

    finalize_kernel<<<(NN * D + 255) / 256, 256>>>(out);
}

// round 4
// speedup vs baseline: 1.0034x; 1.0034x over previous
#include <cuda_runtime.h>
#include <math.h>
#include <stdint.h>

#define NN 50000
#define EE 800000
#define TT 12
#define D  128
#define G4 (4*D)   // 512 gates

// ---------------- scratch (device globals: no allocation allowed) ----------------
__device__ float g_norm_src[NN];
__device__ float g_norm_dst[NN];
__device__ int   g_ocnt[NN];
__device__ int   g_cnt[NN + 1];
__device__ int   g_rowptr[NN + 1];
__device__ int   g_cursor[NN];
__device__ int   g_srcsorted[EE];
__device__ __align__(16) float g_x[(size_t)NN * D];       // layer activations
__device__ __align__(16) float g_m[(size_t)NN * D];       // spmm output
__device__ __align__(16) float g_h0[(size_t)NN * D];      // LSTM h ping
__device__ __align__(16) float g_h1[(size_t)NN * D];      // LSTM h pong
__device__ __align__(16) float g_cstate[(size_t)NN * D];  // LSTM c
__device__ __align__(16) float g_Wl[(size_t)G4 * 256];    // permuted [W_ih|W_hh], quad-interleaved rows
__device__ float g_bias_p[G4];                            // permuted b_ih + b_hh
__device__ float g_hs[TT * D];                            // hs accumulators

// ---------------- helpers ----------------
__device__ __forceinline__ float gelu_exact(float v) {
    return 0.5f * v * (1.0f + erff(v * 0.70710678118654752f));
}
__device__ __forceinline__ float sigmoidf_(float v) {
    return 1.0f / (1.0f + __expf(-v));
}
__device__ __forceinline__ uint32_t f2tf32(float x) {
    uint32_t r;
    asm("cvt.rna.tf32.f32 %0, %1;" : "=r"(r) : "f"(x));
    return r;
}
__device__ __forceinline__ void split_tf32(float x, uint32_t& hi, uint32_t& lo) {
    hi = f2tf32(x);
    lo = f2tf32(x - __uint_as_float(hi));
}
__device__ __forceinline__ void mma8(float (&c)[4], uint4 a, uint32_t b0, uint32_t b1) {
    asm volatile(
        "mma.sync.aligned.m16n8k8.row.col.f32.tf32.tf32.f32 "
        "{%0,%1,%2,%3},{%4,%5,%6,%7},{%8,%9},{%0,%1,%2,%3};\n"
        : "+f"(c[0]), "+f"(c[1]), "+f"(c[2]), "+f"(c[3])
        : "r"(a.x), "r"(a.y), "r"(a.z), "r"(a.w), "r"(b0), "r"(b1));
}

// ---------------- init ----------------
__global__ void init_kernel(float* __restrict__ out_ht) {
    int i = blockIdx.x * blockDim.x + threadIdx.x;
    if (i < NN * D) {
        g_h0[i] = 0.0f;
        g_cstate[i] = 0.0f;
        out_ht[i] = 0.0f;
    }
    if (i < NN) { g_ocnt[i] = 0; g_cnt[i] = 0; }
    if (i == 0) g_cnt[NN] = 0;
    if (i < TT * D) g_hs[i] = 0.0f;
}

__global__ void hist_kernel(const int* __restrict__ src, const int* __restrict__ dst) {
    int e = blockIdx.x * blockDim.x + threadIdx.x;
    if (e < EE) {
        atomicAdd(&g_ocnt[src[e]], 1);
        atomicAdd(&g_cnt[dst[e]], 1);
    }
}

__global__ void norm_kernel() {
    int i = blockIdx.x * blockDim.x + threadIdx.x;
    if (i < NN) {
        g_norm_src[i] = rsqrtf(fmaxf((float)g_ocnt[i], 1.0f));
        g_norm_dst[i] = rsqrtf(fmaxf((float)g_cnt[i], 1.0f));
    }
}

// Build permuted LSTM weight matrix: row (j*4+g) = original row (g*128+j),
// cols 0..127 = w_ih, 128..255 = w_hh. Same permutation for bias.
__global__ void wperm_kernel(const float* __restrict__ w_ih, const float* __restrict__ w_hh,
                             const float* __restrict__ b_ih, const float* __restrict__ b_hh) {
    int idx = blockIdx.x * blockDim.x + threadIdx.x;
    if (idx >= G4 * 256) return;
    int row_out = idx >> 8;
    int k = idx & 255;
    int j = row_out >> 2;
    int g = row_out & 3;
    int row_in = g * D + j;
    float v = (k < D) ? w_ih[row_in * D + k] : w_hh[row_in * D + (k - D)];
    g_Wl[(size_t)row_out * 256 + k] = v;
    if (k == 0) g_bias_p[row_out] = b_ih[row_in] + b_hh[row_in];
}

// single-block exclusive scan of g_cnt[0..NN) -> g_rowptr, init cursor
__global__ void scan_kernel() {
    __shared__ int ps[1024];
    const int CH = (NN + 1023) / 1024;
    int t = threadIdx.x;
    int beg = t * CH;
    int end = min(beg + CH, NN);
    int s = 0;
    for (int i = beg; i < end; i++) s += g_cnt[i];
    ps[t] = s;
    __syncthreads();
    if (t == 0) {
        int a = 0;
        for (int i = 0; i < 1024; i++) { int v = ps[i]; ps[i] = a; a += v; }
    }
    __syncthreads();
    int off = ps[t];
    for (int i = beg; i < end; i++) {
        g_rowptr[i] = off;
        g_cursor[i] = off;
        off += g_cnt[i];
    }
    if (t == 1023) g_rowptr[NN] = off;
}

__global__ void scatter_kernel(const int* __restrict__ src, const int* __restrict__ dst) {
    int e = blockIdx.x * blockDim.x + threadIdx.x;
    if (e < EE) {
        int d = dst[e];
        int p = atomicAdd(&g_cursor[d], 1);
        g_srcsorted[p] = src[e];
    }
}

// ---------------- SpMM: m[d] = norm_dst[d] * sum_{e: dst=d} norm_src[src] * X[src]
__global__ __launch_bounds__(256) void spmm_kernel(const float* __restrict__ X, int ldx,
                                                   float* __restrict__ M) {
    int w = (blockIdx.x * blockDim.x + threadIdx.x) >> 5;
    int lane = threadIdx.x & 31;
    if (w >= NN) return;
    int s0 = g_rowptr[w];
    int s1 = g_rowptr[w + 1];
    float4 acc = make_float4(0.f, 0.f, 0.f, 0.f);
    for (int base = s0; base < s1; base += 32) {
        int n = min(32, s1 - base);
        int s = 0; float ns = 0.f;
        if (lane < n) {
            s = g_srcsorted[base + lane];
            ns = g_norm_src[s];
        }
        for (int j = 0; j < n; j++) {
            int   sj = __shfl_sync(0xffffffffu, s, j);
            float nj = __shfl_sync(0xffffffffu, ns, j);
            float4 v = *(const float4*)(X + (size_t)sj * ldx + lane * 4);
            acc.x += v.x * nj; acc.y += v.y * nj;
            acc.z += v.z * nj; acc.w += v.w * nj;
        }
    }
    float nd = g_norm_dst[w];
    float4 o = make_float4(acc.x * nd, acc.y * nd, acc.z * nd, acc.w * nd);
    *(float4*)(M + (size_t)w * D + lane * 4) = o;
}

// ==================================================================================
// 3xTF32 tensor-core GEMM. BM=128, BN=128, BK=16, 256 threads (8 warps, 2x4),
// warp tile 64x32, mma.m16n8k8. A split into fp32->tf32 hi/lo at staging.
// MODE 0: graph conv  C = gelu(A@B + bias), B is [K][128] row-major (K=128),
//         optional column-sum into hsacc.
// MODE 1: LSTM gates  gates = [x_t | h] @ Wl^T + bias_p (Wl [512][256], quad-permuted),
//         fused cell epilogue updates cstate, hout, htacc. K=256, grid.y=4.
// ==================================================================================
template <int MODE>
__global__ __launch_bounds__(256) void gemm3x_kernel(
    const float* __restrict__ A0, int lda0,    // rows of A, first 128 k-cols
    const float* __restrict__ A1,              // MODE1: h input (ld 128)
    const float* __restrict__ B,
    const float* __restrict__ bias,
    float* __restrict__ C,                     // MODE0 output
    float* __restrict__ hsacc,                 // MODE0 colsum target (or null)
    float* __restrict__ cstate,                // MODE1
    float* __restrict__ hout,                  // MODE1
    float* __restrict__ htacc)                 // MODE1
{
    constexpr int KT = MODE ? 256 : 128;
    __shared__ __align__(16) uint32_t sh[8192];            // 32 KB
    uint32_t* As_hi = sh;                                  // 16 frags * 32 * 4
    uint32_t* As_lo = sh + 2048;
    uint32_t* Bs_hi = sh + 4096;                           // 32 frags * 32 * 2
    uint32_t* Bs_lo = sh + 6144;
    float* gtile = (float*)sh;                             // epilogue: [64][128]

    const int tid = threadIdx.x;
    const int lane = tid & 31;
    const int warpId = tid >> 5;
    const int warpM = warpId >> 2;    // 0..1
    const int warpN = warpId & 3;     // 0..3
    const int rowBase = blockIdx.x * 128;
    const int colBase = blockIdx.y * 128;

    float acc[4][4][4];
#pragma unroll
    for (int a = 0; a < 4; a++)
#pragma unroll
        for (int b = 0; b < 4; b++)
#pragma unroll
            for (int c = 0; c < 4; c++) acc[a][b][c] = 0.f;

    for (int ch = 0; ch < KT / 16; ch++) {
        const int kc = ch * 16;
        // ---- stage A (128 rows x 16 k), split hi/lo, fragment-permuted ----
        {
            int r = tid >> 1;
            int kq = (tid & 1) * 8;
            const float* src;
            int ld, kk;
            if (MODE == 1 && kc >= 128) { src = A1; ld = D; kk = kc - 128 + kq; }
            else                        { src = A0; ld = lda0; kk = kc + kq; }
            int grow = rowBase + r;
            float4 v0 = make_float4(0.f, 0.f, 0.f, 0.f);
            float4 v1 = v0;
            if (grow < NN) {
                v0 = *(const float4*)(src + (size_t)grow * ld + kk);
                v1 = *(const float4*)(src + (size_t)grow * ld + kk + 4);
            }
            float vals[8] = {v0.x, v0.y, v0.z, v0.w, v1.x, v1.y, v1.z, v1.w};
            int mi = r >> 4;
#pragma unroll
            for (int j = 0; j < 8; j++) {
                int kl = kq + j;
                uint32_t hi, lo;
                split_tf32(vals[j], hi, lo);
                int ki = kl >> 3;
                int l = (r & 7) * 4 + (kl & 3);
                int rg = ((r >> 3) & 1) | (((kl >> 2) & 1) << 1);
                int ad = ((mi * 2 + ki) * 32 + l) * 4 + rg;
                As_hi[ad] = hi;
                As_lo[ad] = lo;
            }
        }
        // ---- stage B (16 k x 128 n) ----
        if (MODE == 0) {
            int kb = tid >> 4;
            int n0 = (tid & 15) * 8;
            const float* bp = B + (size_t)(kc + kb) * 128 + n0;
            float4 v0 = *(const float4*)bp;
            float4 v1 = *(const float4*)(bp + 4);
            float vals[8] = {v0.x, v0.y, v0.z, v0.w, v1.x, v1.y, v1.z, v1.w};
            int ki = kb >> 3;
#pragma unroll
            for (int j = 0; j < 8; j++) {
                int n = n0 + j;
                uint32_t hi, lo;
                split_tf32(vals[j], hi, lo);
                int ni = n >> 3;
                int l = (n & 7) * 4 + (kb & 3);
                int rg = (kb >> 2) & 1;
                int ad = ((ni * 2 + ki) * 32 + l) * 2 + rg;
                Bs_hi[ad] = hi;
                Bs_lo[ad] = lo;
            }
        } else {
            int n = tid >> 1;
            int kq = (tid & 1) * 8;
            const float* bp = B + (size_t)(colBase + n) * 256 + kc + kq;
            float4 v0 = *(const float4*)bp;
            float4 v1 = *(const float4*)(bp + 4);
            float vals[8] = {v0.x, v0.y, v0.z, v0.w, v1.x, v1.y, v1.z, v1.w};
            int ni = n >> 3;
#pragma unroll
            for (int j = 0; j < 8; j++) {
                int kl = kq + j;
                uint32_t hi, lo;
                split_tf32(vals[j], hi, lo);
                int ki = kl >> 3;
                int l = (n & 7) * 4 + (kl & 3);
                int rg = (kl >> 2) & 1;
                int ad = ((ni * 2 + ki) * 32 + l) * 2 + rg;
                Bs_hi[ad] = hi;
                Bs_lo[ad] = lo;
            }
        }
        __syncthreads();
        // ---- compute: 2 k8 steps, 3xTF32 ----
#pragma unroll
        for (int ki = 0; ki < 2; ki++) {
            uint4 ah[4], al[4];
#pragma unroll
            for (int mi = 0; mi < 4; mi++) {
                int fid = ((warpM * 4 + mi) * 2 + ki);
                ah[mi] = ((const uint4*)As_hi)[fid * 32 + lane];
                al[mi] = ((const uint4*)As_lo)[fid * 32 + lane];
            }
#pragma unroll
            for (int ni = 0; ni < 4; ni++) {
                int fid = ((warpN * 4 + ni) * 2 + ki);
                uint2 bh = ((const uint2*)Bs_hi)[fid * 32 + lane];
                uint2 bl = ((const uint2*)Bs_lo)[fid * 32 + lane];
#pragma unroll
                for (int mi = 0; mi < 4; mi++) {
                    mma8(acc[mi][ni], ah[mi], bh.x, bh.y);
                    mma8(acc[mi][ni], ah[mi], bl.x, bl.y);
                    mma8(acc[mi][ni], al[mi], bh.x, bh.y);
                }
            }
        }
        __syncthreads();
    }

    // ---- epilogue: stage through shared (coalesced global traffic), 2 row-halves ----
    float csum[4] = {0.f, 0.f, 0.f, 0.f};   // MODE0 colsum (cols fixed per thread)
    const int cq = tid & 31;

    for (int half = 0; half < 2; half++) {
        __syncthreads();
        if (warpM == half) {
#pragma unroll
            for (int mi = 0; mi < 4; mi++) {
#pragma unroll
                for (int ni = 0; ni < 4; ni++) {
                    int rloc = mi * 16 + (lane >> 2);
                    int cloc = warpN * 32 + ni * 8 + (lane & 3) * 2;
                    float b0v = bias[colBase + cloc];
                    float b1v = bias[colBase + cloc + 1];
                    gtile[rloc * 128 + cloc]           = acc[mi][ni][0] + b0v;
                    gtile[rloc * 128 + cloc + 1]       = acc[mi][ni][1] + b1v;
                    gtile[(rloc + 8) * 128 + cloc]     = acc[mi][ni][2] + b0v;
                    gtile[(rloc + 8) * 128 + cloc + 1] = acc[mi][ni][3] + b1v;
                }
            }
        }
        __syncthreads();
#pragma unroll
        for (int i = 0; i < 8; i++) {
            int e = tid + i * 256;
            int rloc = e >> 5;
            int row = rowBase + half * 64 + rloc;
            if (MODE == 0) {
                float4 gv = *(const float4*)&gtile[rloc * 128 + cq * 4];
                float4 ov;
                ov.x = gelu_exact(gv.x);
                ov.y = gelu_exact(gv.y);
                ov.z = gelu_exact(gv.z);
                ov.w = gelu_exact(gv.w);
                if (row < NN) {
                    *(float4*)(C + (size_t)row * D + cq * 4) = ov;
                    csum[0] += ov.x; csum[1] += ov.y; csum[2] += ov.z; csum[3] += ov.w;
                }
            } else {
                if (row < NN) {
                    float4 gv = *(const float4*)&gtile[rloc * 128 + cq * 4];
                    int fg = blockIdx.y * 32 + cq;
                    size_t idx = (size_t)row * D + fg;
                    float cp = cstate[idx];
                    float c = sigmoidf_(gv.y) * cp + sigmoidf_(gv.x) * tanhf(gv.z);
                    float ho = sigmoidf_(gv.w) * tanhf(c);
                    cstate[idx] = c;
                    hout[idx] = ho;
                    htacc[idx] += ho;
                }
            }
        }
    }
    if (MODE == 0 && hsacc != nullptr) {
#pragma unroll
        for (int j = 0; j < 4; j++) atomicAdd(&hsacc[cq * 4 + j], csum[j]);
    }
}

__global__ void finalize_kernel(float* __restrict__ out) {
    int idx = blockIdx.x * blockDim.x + threadIdx.x;
    if (idx < TT * D) out[idx] = g_hs[idx] * (1.0f / (float)NN);
    if (idx < NN * D) out[TT * D + idx] *= (1.0f / (float)TT);
}

// ---------------- launch ----------------
extern "C" void kernel_launch(void* const* d_in, const int* in_sizes, int n_in,
                              void* d_out, int out_size) {
    const float* h    = (const float*)d_in[0];
    const int*   src  = (const int*)d_in[1];
    const int*   dst  = (const int*)d_in[2];
    const float* Wg1  = (const float*)d_in[3];
    const float* bg1  = (const float*)d_in[4];
    const float* Wg2  = (const float*)d_in[5];
    const float* bg2  = (const float*)d_in[6];
    const float* w_ih = (const float*)d_in[7];
    const float* w_hh = (const float*)d_in[8];
    const float* b_ih = (const float*)d_in[9];
    const float* b_hh = (const float*)d_in[10];

    float* out    = (float*)d_out;
    float* out_ht = out + TT * D;

    float *pm, *px, *ph0, *ph1, *pc, *pwl, *pbp, *phs;
    cudaGetSymbolAddress((void**)&pm, g_m);
    cudaGetSymbolAddress((void**)&px, g_x);
    cudaGetSymbolAddress((void**)&ph0, g_h0);
    cudaGetSymbolAddress((void**)&ph1, g_h1);
    cudaGetSymbolAddress((void**)&pc, g_cstate);
    cudaGetSymbolAddress((void**)&pwl, g_Wl);
    cudaGetSymbolAddress((void**)&pbp, g_bias_p);
    cudaGetSymbolAddress((void**)&phs, g_hs);

    init_kernel<<<(NN * D + 255) / 256, 256>>>(out_ht);
    hist_kernel<<<(EE + 255) / 256, 256>>>(src, dst);
    norm_kernel<<<(NN + 255) / 256, 256>>>();
    wperm_kernel<<<(G4 * 256 + 255) / 256, 256>>>(w_ih, w_hh, b_ih, b_hh);
    scan_kernel<<<1, 1024>>>();
    scatter_kernel<<<(EE + 255) / 256, 256>>>(src, dst);

    const int gx = (NN + 127) / 128;           // 391
    dim3 ggrid(gx, 1);
    dim3 lgrid(gx, 4);
    int spmm_blocks = (NN * 32 + 255) / 256;

    // graph conv tower
    for (int t = 0; t < TT; t++) {
        spmm_kernel<<<spmm_blocks, 256>>>(h + t * D, TT * D, pm);
        gemm3x_kernel<0><<<ggrid, 256>>>(pm, D, nullptr, Wg1, bg1, px, nullptr,
                                         nullptr, nullptr, nullptr);
        spmm_kernel<<<spmm_blocks, 256>>>(px, D, pm);
        gemm3x_kernel<0><<<ggrid, 256>>>(pm, D, nullptr, Wg2, bg2, px, phs + t * D,
                                         nullptr, nullptr, nullptr);
    }

    // LSTM over T steps (fused gates GEMM + cell epilogue), h ping-pong
    float* hin = ph0;
    float* hout_ = ph1;
    for (int t = 0; t < TT; t++) {
        gemm3x_kernel<1><<<lgrid, 256>>>(h + t * D, TT * D, hin, pwl, pbp,
                                         nullptr, nullptr, pc, hout_, out_ht);
        float* tmp = hin; hin = hout_; hout_ = tmp;
    }

    finalize_kernel<<<(NN * D + 255) / 256, 256>>>(out);
}

// round 7
// speedup vs baseline: 1.4700x; 1.4650x over previous
#include <cuda_runtime.h>
#include <cuda_bf16.h>
#include <math.h>
#include <stdint.h>

#define NN 50000
#define EE 800000
#define TT 12
#define D  128

typedef unsigned short u16;
typedef unsigned int   u32;

// ---------------- scratch ----------------
__device__ float g_norm_src[NN], g_norm_dst[NN];
__device__ int g_ocnt[NN], g_cnt[NN + 1], g_rowptr[NN + 1], g_cursor[NN];
__device__ int g_srcsorted[EE];
__device__ __align__(16) u16 g_xhi[(size_t)NN * TT * D];   // h pre-split (pair-packed along k)
__device__ __align__(16) u16 g_xlo[(size_t)NN * TT * D];
__device__ __align__(16) u16 g_mhi[(size_t)NN * D];        // spmm out
__device__ __align__(16) u16 g_mlo[(size_t)NN * D];
__device__ __align__(16) float g_xact[(size_t)NN * D];     // layer-1 act (fp32, spmm2 input)
__device__ __align__(16) u16 g_hhi0[(size_t)NN * D], g_hlo0[(size_t)NN * D];
__device__ __align__(16) u16 g_hhi1[(size_t)NN * D], g_hlo1[(size_t)NN * D];
__device__ __align__(16) float g_c[(size_t)NN * D];
__device__ __align__(16) u16 g_wlhi[512 * 256], g_wllo[512 * 256];  // [n][k], quad-permuted rows
__device__ __align__(16) u16 g_w1hi[128 * 128], g_w1lo[128 * 128];  // [n][k]
__device__ __align__(16) u16 g_w2hi[128 * 128], g_w2lo[128 * 128];
__device__ float g_biasp[512];
__device__ float g_hs[TT * D];

// ---------------- helpers ----------------
__device__ __forceinline__ float gelu_exact(float v) {
    return 0.5f * v * (1.0f + erff(v * 0.70710678118654752f));
}
__device__ __forceinline__ float sigmoidf_(float v) {
    return 1.0f / (1.0f + __expf(-v));
}
__device__ __forceinline__ void bsplit(float x, u16& h, u16& l) {
    __nv_bfloat16 bh = __float2bfloat16(x);
    float hr = __bfloat162float(bh);
    __nv_bfloat16 bl = __float2bfloat16(x - hr);
    h = *(u16*)&bh;
    l = *(u16*)&bl;
}
__device__ __forceinline__ void mma16(float (&c)[4], uint4 a, u32 b0, u32 b1) {
    asm volatile(
        "mma.sync.aligned.m16n8k16.row.col.f32.bf16.bf16.f32 "
        "{%0,%1,%2,%3},{%4,%5,%6,%7},{%8,%9},{%0,%1,%2,%3};\n"
        : "+f"(c[0]), "+f"(c[1]), "+f"(c[2]), "+f"(c[3])
        : "r"(a.x), "r"(a.y), "r"(a.z), "r"(a.w), "r"(b0), "r"(b1));
}

// ---------------- setup kernels ----------------
__global__ void init_kernel(float* __restrict__ out_ht) {
    int i = blockIdx.x * blockDim.x + threadIdx.x;
    if (i < NN * D) {
        g_c[i] = 0.0f;
        g_hhi0[i] = 0; g_hlo0[i] = 0;
        out_ht[i] = 0.0f;
    }
    if (i < NN) { g_ocnt[i] = 0; g_cnt[i] = 0; }
    if (i == 0) g_cnt[NN] = 0;
    if (i < TT * D) g_hs[i] = 0.0f;
}
__global__ void hist_kernel(const int* __restrict__ src, const int* __restrict__ dst) {
    int e = blockIdx.x * blockDim.x + threadIdx.x;
    if (e < EE) {
        atomicAdd(&g_ocnt[src[e]], 1);
        atomicAdd(&g_cnt[dst[e]], 1);
    }
}
__global__ void norm_kernel() {
    int i = blockIdx.x * blockDim.x + threadIdx.x;
    if (i < NN) {
        g_norm_src[i] = rsqrtf(fmaxf((float)g_ocnt[i], 1.0f));
        g_norm_dst[i] = rsqrtf(fmaxf((float)g_cnt[i], 1.0f));
    }
}
__global__ void scan_kernel() {
    __shared__ int ps[1024];
    const int CH = (NN + 1023) / 1024;
    int t = threadIdx.x;
    int beg = t * CH, end = min(beg + CH, NN);
    int s = 0;
    for (int i = beg; i < end; i++) s += g_cnt[i];
    ps[t] = s;
    __syncthreads();
    if (t == 0) {
        int a = 0;
        for (int i = 0; i < 1024; i++) { int v = ps[i]; ps[i] = a; a += v; }
    }
    __syncthreads();
    int off = ps[t];
    for (int i = beg; i < end; i++) {
        g_rowptr[i] = off;
        g_cursor[i] = off;
        off += g_cnt[i];
    }
    if (t == 1023) g_rowptr[NN] = off;
}
__global__ void scatter_kernel(const int* __restrict__ src, const int* __restrict__ dst) {
    int e = blockIdx.x * blockDim.x + threadIdx.x;
    if (e < EE) {
        int d = dst[e];
        int p = atomicAdd(&g_cursor[d], 1);
        g_srcsorted[p] = src[e];
    }
}
__global__ void convh_kernel(const float* __restrict__ h) {
    size_t q = (size_t)blockIdx.x * blockDim.x + threadIdx.x;
    if (q >= (size_t)NN * TT * D / 4) return;
    float4 v = ((const float4*)h)[q];
    u16 h0, h1, h2, h3, l0, l1, l2, l3;
    bsplit(v.x, h0, l0); bsplit(v.y, h1, l1);
    bsplit(v.z, h2, l2); bsplit(v.w, h3, l3);
    ((uint2*)g_xhi)[q] = make_uint2((u32)h0 | ((u32)h1 << 16), (u32)h2 | ((u32)h3 << 16));
    ((uint2*)g_xlo)[q] = make_uint2((u32)l0 | ((u32)l1 << 16), (u32)l2 | ((u32)l3 << 16));
}
// LSTM weights: row_out j*4+g <- row_in g*128+j, cols [w_ih|w_hh]
__global__ void wlprep_kernel(const float* __restrict__ w_ih, const float* __restrict__ w_hh,
                              const float* __restrict__ b_ih, const float* __restrict__ b_hh) {
    int idx = blockIdx.x * blockDim.x + threadIdx.x;
    if (idx >= 512 * 256) return;
    int ro = idx >> 8, k = idx & 255;
    int ri = (ro & 3) * D + (ro >> 2);
    float v = (k < D) ? w_ih[ri * D + k] : w_hh[ri * D + (k - D)];
    u16 hh, ll;
    bsplit(v, hh, ll);
    g_wlhi[idx] = hh; g_wllo[idx] = ll;
    if (k == 0) g_biasp[ro] = b_ih[ri] + b_hh[ri];
}
// graph weights: B[n][k] = W[k][n]
__global__ void wgprep_kernel(const float* __restrict__ Wg1, const float* __restrict__ Wg2) {
    int idx = blockIdx.x * blockDim.x + threadIdx.x;
    if (idx >= 2 * 128 * 128) return;
    int sel = idx >> 14, e = idx & 16383;
    int n = e >> 7, k = e & 127;
    float v = sel ? Wg2[k * 128 + n] : Wg1[k * 128 + n];
    u16 hh, ll;
    bsplit(v, hh, ll);
    if (sel) { g_w2hi[e] = hh; g_w2lo[e] = ll; }
    else     { g_w1hi[e] = hh; g_w1lo[e] = ll; }
}

// ---------------- SpMM: emits bf16 hi/lo pairs ----------------
__global__ __launch_bounds__(256) void spmm_kernel(const float* __restrict__ X, int ldx) {
    int w = (blockIdx.x * blockDim.x + threadIdx.x) >> 5;
    int lane = threadIdx.x & 31;
    if (w >= NN) return;
    int s0 = g_rowptr[w], s1 = g_rowptr[w + 1];
    float4 acc = make_float4(0.f, 0.f, 0.f, 0.f);
    for (int base = s0; base < s1; base += 32) {
        int n = min(32, s1 - base);
        int s = 0; float ns = 0.f;
        if (lane < n) {
            s = g_srcsorted[base + lane];
            ns = g_norm_src[s];
        }
        for (int j = 0; j < n; j++) {
            int   sj = __shfl_sync(0xffffffffu, s, j);
            float nj = __shfl_sync(0xffffffffu, ns, j);
            float4 v = *(const float4*)(X + (size_t)sj * ldx + lane * 4);
            acc.x += v.x * nj; acc.y += v.y * nj;
            acc.z += v.z * nj; acc.w += v.w * nj;
        }
    }
    float nd = g_norm_dst[w];
    u16 h0, h1, h2, h3, l0, l1, l2, l3;
    bsplit(acc.x * nd, h0, l0); bsplit(acc.y * nd, h1, l1);
    bsplit(acc.z * nd, h2, l2); bsplit(acc.w * nd, h3, l3);
    size_t q = ((size_t)w * D + lane * 4) >> 2;
    ((uint2*)g_mhi)[q] = make_uint2((u32)h0 | ((u32)h1 << 16), (u32)h2 | ((u32)h3 << 16));
    ((uint2*)g_mlo)[q] = make_uint2((u32)l0 | ((u32)l1 << 16), (u32)l2 | ((u32)l3 << 16));
}

// ==================================================================================
// bf16 3-term split GEMM with legacy mma.m16n8k16. BM=128, BN=128, BK=16.
// 256 threads: 8 warps (2x4), warp tile 64x32 (4x4 m16n8 frags).
// A/B staged from PRE-SPLIT pair-packed bf16 arrays (u32 = 2 bf16 along k).
// MODE 0: graph conv, K=128: C = gelu(A@B^T + bias); opt C store, opt hs colsum.
// MODE 1: LSTM, K=256 (A = [x_t | h]): fused cell epilogue. grid.y = 4.
// ==================================================================================
template <int MODE>
__global__ __launch_bounds__(256) void gemm_bf16(
    const u32* __restrict__ A0h, const u32* __restrict__ A0l, int ldap,   // pairs/row
    const u32* __restrict__ A1h, const u32* __restrict__ A1l,             // MODE1 h (ld 64)
    const u32* __restrict__ Bh,  const u32* __restrict__ Bl,  int ldbp,
    const float* __restrict__ bias,
    float* __restrict__ C, float* __restrict__ hsacc,
    float* __restrict__ cst, u16* __restrict__ hoh, u16* __restrict__ hol,
    float* __restrict__ hta)
{
    __shared__ __align__(16) u32 sh[8192];            // 32 KB
    u32* As_hi = sh;          // [8 frag][32 lane][4 reg]
    u32* As_lo = sh + 1024;
    u32* Bs_hi = sh + 2048;   // [16 frag][32 lane][2 reg]
    u32* Bs_lo = sh + 3072;
    float* gtile = (float*)sh;                        // epilogue [64][128]

    const int tid = threadIdx.x, lane = tid & 31;
    const int warpId = tid >> 5;
    const int warpM = warpId >> 2, warpN = warpId & 3;
    const int rowBase = blockIdx.x * 128;
    const int colBase = blockIdx.y * 128;

    float acc[4][4][4];
#pragma unroll
    for (int a = 0; a < 4; a++)
#pragma unroll
        for (int b = 0; b < 4; b++)
#pragma unroll
            for (int c = 0; c < 4; c++) acc[a][b][c] = 0.f;

    const int NCH = MODE ? 16 : 8;
    const int r_ = tid >> 1, halfk = (tid & 1) * 4;   // staging coords
    for (int ch = 0; ch < NCH; ch++) {
        // ---- stage A: 128 rows x 8 pairs, hi+lo ----
        {
            const u32 *sh_, *sl_;
            int po;
            if (MODE == 1 && ch >= 8) { sh_ = A1h; sl_ = A1l; po = (ch - 8) * 8 + halfk; }
            else                      { sh_ = A0h; sl_ = A0l; po = ch * 8 + halfk; }
            int ld = (MODE == 1 && ch >= 8) ? 64 : ldap;
            uint4 vh = make_uint4(0, 0, 0, 0), vl = vh;
            if (rowBase + r_ < NN) {
                vh = *(const uint4*)(sh_ + (size_t)(rowBase + r_) * ld + po);
                vl = *(const uint4*)(sl_ + (size_t)(rowBase + r_) * ld + po);
            }
            u32 ph[4] = {vh.x, vh.y, vh.z, vh.w};
            u32 pl[4] = {vl.x, vl.y, vl.z, vl.w};
            int m = r_ >> 4, row16 = r_ & 15;
#pragma unroll
            for (int j = 0; j < 4; j++) {
                int kp = halfk + j;
                int l = (row16 & 7) * 4 + (kp & 3);
                int rg = (row16 >> 3) | ((kp >> 2) << 1);
                int ad = (m * 32 + l) * 4 + rg;
                As_hi[ad] = ph[j];
                As_lo[ad] = pl[j];
            }
        }
        // ---- stage B: 128 cols x 8 pairs ----
        {
            int gc = (MODE ? colBase : 0) + r_;
            int po = ch * 8 + halfk;
            uint4 vh = *(const uint4*)(Bh + (size_t)gc * ldbp + po);
            uint4 vl = *(const uint4*)(Bl + (size_t)gc * ldbp + po);
            u32 ph[4] = {vh.x, vh.y, vh.z, vh.w};
            u32 pl[4] = {vl.x, vl.y, vl.z, vl.w};
            int n = r_ >> 3;
#pragma unroll
            for (int j = 0; j < 4; j++) {
                int kp = halfk + j;
                int l = (r_ & 7) * 4 + (kp & 3);
                int rg = kp >> 2;
                int ad = (n * 32 + l) * 2 + rg;
                Bs_hi[ad] = ph[j];
                Bs_lo[ad] = pl[j];
            }
        }
        __syncthreads();
        // ---- compute ----
        uint4 ah[4], al[4];
#pragma unroll
        for (int mi = 0; mi < 4; mi++) {
            int fid = warpM * 4 + mi;
            ah[mi] = ((const uint4*)As_hi)[fid * 32 + lane];
            al[mi] = ((const uint4*)As_lo)[fid * 32 + lane];
        }
#pragma unroll
        for (int ni = 0; ni < 4; ni++) {
            int fid = warpN * 4 + ni;
            uint2 bh = ((const uint2*)Bs_hi)[fid * 32 + lane];
            uint2 bl = ((const uint2*)Bs_lo)[fid * 32 + lane];
#pragma unroll
            for (int mi = 0; mi < 4; mi++) {
                mma16(acc[mi][ni], ah[mi], bh.x, bh.y);
                mma16(acc[mi][ni], ah[mi], bl.x, bl.y);
                mma16(acc[mi][ni], al[mi], bh.x, bh.y);
            }
        }
        __syncthreads();
    }

    // ---- epilogue: stage through shared, 2 row-halves of 64 ----
    float csum[4] = {0.f, 0.f, 0.f, 0.f};
    const int cq = tid & 31;

    for (int half = 0; half < 2; half++) {
        __syncthreads();
        if (warpM == half) {
#pragma unroll
            for (int mi = 0; mi < 4; mi++) {
#pragma unroll
                for (int ni = 0; ni < 4; ni++) {
                    int rloc = mi * 16 + (lane >> 2);
                    int cloc = warpN * 32 + ni * 8 + (lane & 3) * 2;
                    float b0v = bias[colBase + cloc];
                    float b1v = bias[colBase + cloc + 1];
                    gtile[rloc * 128 + cloc]           = acc[mi][ni][0] + b0v;
                    gtile[rloc * 128 + cloc + 1]       = acc[mi][ni][1] + b1v;
                    gtile[(rloc + 8) * 128 + cloc]     = acc[mi][ni][2] + b0v;
                    gtile[(rloc + 8) * 128 + cloc + 1] = acc[mi][ni][3] + b1v;
                }
            }
        }
        __syncthreads();
#pragma unroll
        for (int i = 0; i < 8; i++) {
            int e = tid + i * 256;
            int rloc = e >> 5;
            int row = rowBase + half * 64 + rloc;
            if (MODE == 0) {
                float4 gv = *(const float4*)&gtile[rloc * 128 + cq * 4];
                float4 ov;
                ov.x = gelu_exact(gv.x);
                ov.y = gelu_exact(gv.y);
                ov.z = gelu_exact(gv.z);
                ov.w = gelu_exact(gv.w);
                if (row < NN) {
                    if (C != nullptr)
                        *(float4*)(C + (size_t)row * D + cq * 4) = ov;
                    csum[0] += ov.x; csum[1] += ov.y; csum[2] += ov.z; csum[3] += ov.w;
                }
            } else {
                if (row < NN) {
                    float4 gv = *(const float4*)&gtile[rloc * 128 + cq * 4];
                    int fg = blockIdx.y * 32 + cq;
                    size_t idx = (size_t)row * D + fg;
                    float cp = g_c[idx];
                    float cn = sigmoidf_(gv.y) * cp + sigmoidf_(gv.x) * tanhf(gv.z);
                    float ho = sigmoidf_(gv.w) * tanhf(cn);
                    g_c[idx] = cn;
                    hta[idx] += ho;
                    u16 hh, hl;
                    bsplit(ho, hh, hl);
                    hoh[idx] = hh;
                    hol[idx] = hl;
                }
            }
        }
    }
    if (MODE == 0 && hsacc != nullptr) {
#pragma unroll
        for (int j = 0; j < 4; j++) atomicAdd(&hsacc[cq * 4 + j], csum[j]);
    }
}

__global__ void finalize_kernel(float* __restrict__ out) {
    int idx = blockIdx.x * blockDim.x + threadIdx.x;
    if (idx < TT * D) out[idx] = g_hs[idx] * (1.0f / (float)NN);
    if (idx < NN * D) out[TT * D + idx] *= (1.0f / (float)TT);
}

// ---------------- launch ----------------
extern "C" void kernel_launch(void* const* d_in, const int* in_sizes, int n_in,
                              void* d_out, int out_size) {
    const float* h    = (const float*)d_in[0];
    const int*   src  = (const int*)d_in[1];
    const int*   dst  = (const int*)d_in[2];
    const float* Wg1  = (const float*)d_in[3];
    const float* bg1  = (const float*)d_in[4];
    const float* Wg2  = (const float*)d_in[5];
    const float* bg2  = (const float*)d_in[6];
    const float* w_ih = (const float*)d_in[7];
    const float* w_hh = (const float*)d_in[8];
    const float* b_ih = (const float*)d_in[9];
    const float* b_hh = (const float*)d_in[10];

    float* out    = (float*)d_out;
    float* out_ht = out + TT * D;

    u16 *pxhi, *pxlo, *pmhi, *pmlo, *ph0h, *ph0l, *ph1h, *ph1l;
    u16 *pwlh, *pwll, *pw1h, *pw1l, *pw2h, *pw2l;
    float *pxact, *pbp, *phs;
    cudaGetSymbolAddress((void**)&pxhi, g_xhi);
    cudaGetSymbolAddress((void**)&pxlo, g_xlo);
    cudaGetSymbolAddress((void**)&pmhi, g_mhi);
    cudaGetSymbolAddress((void**)&pmlo, g_mlo);
    cudaGetSymbolAddress((void**)&ph0h, g_hhi0);
    cudaGetSymbolAddress((void**)&ph0l, g_hlo0);
    cudaGetSymbolAddress((void**)&ph1h, g_hhi1);
    cudaGetSymbolAddress((void**)&ph1l, g_hlo1);
    cudaGetSymbolAddress((void**)&pwlh, g_wlhi);
    cudaGetSymbolAddress((void**)&pwll, g_wllo);
    cudaGetSymbolAddress((void**)&pw1h, g_w1hi);
    cudaGetSymbolAddress((void**)&pw1l, g_w1lo);
    cudaGetSymbolAddress((void**)&pw2h, g_w2hi);
    cudaGetSymbolAddress((void**)&pw2l, g_w2lo);
    cudaGetSymbolAddress((void**)&pxact, g_xact);
    cudaGetSymbolAddress((void**)&pbp, g_biasp);
    cudaGetSymbolAddress((void**)&phs, g_hs);

    init_kernel<<<(NN * D + 255) / 256, 256>>>(out_ht);
    hist_kernel<<<(EE + 255) / 256, 256>>>(src, dst);
    norm_kernel<<<(NN + 255) / 256, 256>>>();
    wlprep_kernel<<<(512 * 256 + 255) / 256, 256>>>(w_ih, w_hh, b_ih, b_hh);
    wgprep_kernel<<<(2 * 128 * 128 + 255) / 256, 256>>>(Wg1, Wg2);
    scan_kernel<<<1, 1024>>>();
    scatter_kernel<<<(EE + 255) / 256, 256>>>(src, dst);
    convh_kernel<<<(int)(((size_t)NN * TT * D / 4 + 255) / 256), 256>>>(h);

    const int gx = (NN + 127) / 128;   // 391
    int spmm_blocks = (NN * 32 + 255) / 256;

    // graph conv tower
    for (int t = 0; t < TT; t++) {
        spmm_kernel<<<spmm_blocks, 256>>>(h + t * D, TT * D);
        gemm_bf16<0><<<dim3(gx, 1), 256>>>((u32*)pmhi, (u32*)pmlo, 64, nullptr, nullptr,
                                           (u32*)pw1h, (u32*)pw1l, 64, bg1,
                                           pxact, nullptr,
                                           nullptr, nullptr, nullptr, nullptr);
        spmm_kernel<<<spmm_blocks, 256>>>(pxact, D);
        gemm_bf16<0><<<dim3(gx, 1), 256>>>((u32*)pmhi, (u32*)pmlo, 64, nullptr, nullptr,
                                           (u32*)pw2h, (u32*)pw2l, 64, bg2,
                                           nullptr, phs + t * D,
                                           nullptr, nullptr, nullptr, nullptr);
    }

    // LSTM (fused gates GEMM + cell epilogue), h bf16 hi/lo ping-pong
    u16 *hih = ph0h, *hil = ph0l, *hoh = ph1h, *hol = ph1l;
    for (int t = 0; t < TT; t++) {
        gemm_bf16<1><<<dim3(gx, 4), 256>>>((u32*)(pxhi) + (size_t)t * 64, (u32*)(pxlo) + (size_t)t * 64,
                                           TT * 64,
                                           (u32*)hih, (u32*)hil,
                                           (u32*)pwlh, (u32*)pwll, 128, pbp,
                                           nullptr, nullptr,
                                           nullptr, hoh, hol, out_ht);
        u16* t1 = hih; hih = hoh; hoh = t1;
        u16* t2 = hil; hil = hol; hol = t2;
    }

    finalize_kernel<<<(NN * D + 255) / 256, 256>>>(out);
}